// round 5
// baseline (speedup 1.0000x reference)
#include <cuda_runtime.h>
#include <cuda_bf16.h>

// GCN 2-layer: N=100000, E=1600000, 64 features.
// ONE persistent preprocessing kernel (grid-barrier phases: zero/detect ->
// count -> chunk scan+dinv -> chunk-sum scan -> finalize -> edge fill),
// then per layer: f32x2 GEMM -> pull aggregation (warp/node, SoA edges,
// vectorized payload, 8 gathers in flight). 5 kernel launches total.

#define NN 100000
#define EE 1600000
#define FD 64
#define TPB 256
#define NBLK 592                          // 148 SMs x 4 blocks (co-resident)
#define NCHUNK ((NN + 255) / 256)         // 391

typedef unsigned long long ull;

// -------- device scratch --------
__device__ unsigned g_barcnt;             // monotonic; no reset needed
__device__ int   g_is64;
__device__ int   g_cnt[NN];
__device__ int   g_cursor[NN];
__device__ float g_dinv[NN];
__device__ int   g_rowptr[NN + 1];
__device__ int   g_csum[NCHUNK];
__device__ __align__(16) int   g_esrc[EE];
__device__ __align__(16) float g_enorm[EE];
__device__ float g_h[NN * FD];
__device__ float g_a[NN * FD];
__device__ float g_h2[NN * FD];

__device__ __forceinline__ int edge_at(const int* __restrict__ ei,
                                       long long pos, int is64) {
    if (is64) return (int)((const long long* __restrict__)ei)[pos];
    return ei[pos];
}

__device__ __forceinline__ void fma2(ull& d, ull a, ull b) {
    asm("fma.rn.f32x2 %0, %1, %2, %0;" : "+l"(d) : "l"(a), "l"(b));
}

// grid barrier: cumulative counter, round-up target -> replay-safe, no reset
__device__ __forceinline__ void gbar() {
    __syncthreads();
    if (threadIdx.x == 0) {
        __threadfence();
        unsigned my = atomicAdd(&g_barcnt, 1u) + 1u;
        unsigned target = ((my + NBLK - 1u) / NBLK) * NBLK;
        while (*(volatile unsigned*)&g_barcnt < target) { }
        __threadfence();
    }
    __syncthreads();
}

// -------- fused preprocessing (persistent, 592 blocks x 256 threads) -----
__global__ __launch_bounds__(TPB) void k_preprocess(
    const int* __restrict__ ei, int n, int E)
{
    __shared__ int sb[2][512];
    const int gtid = blockIdx.x * TPB + threadIdx.x;
    const int gstride = NBLK * TPB;

    // P0: zero counters; detect edge dtype (int64 vals <2^31 -> odd words 0)
    for (int i = gtid; i < n; i += gstride) { g_cnt[i] = 0; g_cursor[i] = 0; }
    if (gtid == 0) {
        int any = 0;
        for (int j = 1; j < 512; j += 2) any |= ei[j];
        g_is64 = (any == 0) ? 1 : 0;
    }
    gbar();
    const int is64 = g_is64;

    // P1: count in-degree (dst)
    for (int e = gtid; e < E; e += gstride) {
        int d = edge_at(ei, (long long)E + e, is64);
        if ((unsigned)d < (unsigned)n) atomicAdd(&g_cnt[d], 1);
    }
    gbar();

    // P2: per-256-chunk scan (block bid handles chunk bid; NCHUNK < NBLK)
    if (blockIdx.x < NCHUNK) {
        int t = threadIdx.x;
        int gid = blockIdx.x * 256 + t;
        int v = (gid < n) ? g_cnt[gid] : 0;
        if (gid < n) g_dinv[gid] = rsqrtf((float)(v + 1));   // +1 self-loop
        sb[0][t] = v;
        __syncthreads();
        int cur = 0;
        #pragma unroll
        for (int off = 1; off < 256; off <<= 1) {
            sb[cur ^ 1][t] = sb[cur][t] + ((t >= off) ? sb[cur][t - off] : 0);
            cur ^= 1;
            __syncthreads();
        }
        int incl = sb[cur][t];
        if (gid < n) g_rowptr[gid] = incl - v;               // chunk-local excl
        if (t == 255) g_csum[blockIdx.x] = incl;
    }
    gbar();

    // P3: block 0 exclusive-scans the 391 chunk sums
    if (blockIdx.x == 0) {
        int t = threadIdx.x;
        int a = (t < NCHUNK) ? g_csum[t] : 0;
        int b = (t + 256 < NCHUNK) ? g_csum[t + 256] : 0;
        sb[0][t] = a; sb[0][t + 256] = b;
        __syncthreads();
        int cur = 0;
        #pragma unroll
        for (int off = 1; off < 512; off <<= 1) {
            int v0 = sb[cur][t]       + ((t >= off) ? sb[cur][t - off] : 0);
            int v1 = sb[cur][t + 256] + ((t + 256 >= off) ? sb[cur][t + 256 - off] : 0);
            sb[cur ^ 1][t] = v0; sb[cur ^ 1][t + 256] = v1;
            cur ^= 1;
            __syncthreads();
        }
        if (t < NCHUNK)       g_csum[t]       = sb[cur][t] - a;
        if (t + 256 < NCHUNK) g_csum[t + 256] = sb[cur][t + 256] - b;
    }
    gbar();

    // P4: finalize rowptr
    for (int i = gtid; i < n; i += gstride) g_rowptr[i] += g_csum[i >> 8];
    if (gtid == 0) g_rowptr[n] = E;
    gbar();

    // P5: bucket edges (SoA payload)
    for (int e = gtid; e < E; e += gstride) {
        int s = edge_at(ei, e, is64);
        int d = edge_at(ei, (long long)E + e, is64);
        if ((unsigned)s >= (unsigned)n || (unsigned)d >= (unsigned)n) continue;
        float nm = g_dinv[s] * g_dinv[d];
        int pos = g_rowptr[d] + atomicAdd(&g_cursor[d], 1);
        g_esrc[pos]  = s;
        g_enorm[pos] = nm;
    }
}

// -------- GEMM: H[n,64] = X[n,64] @ W[64,64], 8x8 f32x2 blocking ---------
template <int LAYER>
__global__ __launch_bounds__(64) void k_gemm(
    const float* __restrict__ Xin, const float* __restrict__ W, int n)
{
    const float* __restrict__ X = (LAYER == 0) ? Xin : (const float*)g_a;
    float* __restrict__ H = (LAYER == 0) ? g_h : g_h2;

    __shared__ float sX[FD][FD + 1];
    __shared__ float sW[FD][FD];
    int t = threadIdx.x;
    int row0 = blockIdx.x * FD;

    for (int i = t * 4; i < FD * FD; i += 64 * 4)
        *(float4*)&sW[i >> 6][i & 63] = *(const float4*)&W[i];
    for (int i4 = t; i4 < (FD * FD) / 4; i4 += 64) {
        int r = i4 >> 4, c = (i4 & 15) * 4;
        float4 v = (row0 + r < n) ? *(const float4*)&X[(size_t)(row0 + r) * FD + c]
                                  : make_float4(0.f, 0.f, 0.f, 0.f);
        sX[r][c] = v.x; sX[r][c + 1] = v.y; sX[r][c + 2] = v.z; sX[r][c + 3] = v.w;
    }
    __syncthreads();

    int c0 = (t & 7) * 8;
    int r0 = (t >> 3) * 8;
    ull acc[8][4];
    #pragma unroll
    for (int i = 0; i < 8; i++)
        #pragma unroll
        for (int j = 0; j < 4; j++) acc[i][j] = 0ull;

    #pragma unroll
    for (int k = 0; k < FD; k++) {
        union { float4 f; ull u[2]; } wa, wb;
        wa.f = *(const float4*)&sW[k][c0];
        wb.f = *(const float4*)&sW[k][c0 + 4];
        ull w0 = wa.u[0], w1 = wa.u[1], w2 = wb.u[0], w3 = wb.u[1];
        #pragma unroll
        for (int i = 0; i < 8; i++) {
            float xv = sX[r0 + i][k];
            ull xp;
            asm("mov.b64 %0, {%1, %1};" : "=l"(xp) : "f"(xv));
            fma2(acc[i][0], xp, w0);
            fma2(acc[i][1], xp, w1);
            fma2(acc[i][2], xp, w2);
            fma2(acc[i][3], xp, w3);
        }
    }

    #pragma unroll
    for (int i = 0; i < 8; i++) {
        int r = row0 + r0 + i;
        if (r < n) {
            union { float4 f; ull u[2]; } lo, hi;
            lo.u[0] = acc[i][0]; lo.u[1] = acc[i][1];
            hi.u[0] = acc[i][2]; hi.u[1] = acc[i][3];
            *(float4*)&H[(size_t)r * FD + c0]     = lo.f;
            *(float4*)&H[(size_t)r * FD + c0 + 4] = hi.f;
        }
    }
}

// -------- pull aggregation: warp/node, vectorized payload, 8 gathers -----
template <int LAYER>
__global__ __launch_bounds__(256) void k_aggregate(
    const float* __restrict__ b, float* __restrict__ outp, int n)
{
    int node = (blockIdx.x * blockDim.x + threadIdx.x) >> 5;
    int lane = threadIdx.x & 31;
    if (node >= n) return;

    const float2* __restrict__ H2 =
        (LAYER == 0) ? (const float2*)g_h : (const float2*)g_h2;
    float2* __restrict__ O2 =
        (LAYER == 0) ? (float2*)g_a : (float2*)outp;

    float2 bb = ((const float2*)b)[lane];
    float  di = g_dinv[node];
    float  w  = di * di;                       // self-loop norm
    float2 hs = H2[(size_t)node * 32 + lane];
    float ax = fmaf(hs.x, w, bb.x);
    float ay = fmaf(hs.y, w, bb.y);

    int e  = g_rowptr[node];
    int e1 = g_rowptr[node + 1];

    while (e < e1 && (e & 3)) {                // align to 16B
        int s = g_esrc[e]; float nm = g_enorm[e];
        float2 hv = H2[(size_t)s * 32 + lane];
        ax = fmaf(hv.x, nm, ax); ay = fmaf(hv.y, nm, ay);
        e++;
    }
    for (; e + 8 <= e1; e += 8) {
        int4   sA = *(const int4*)&g_esrc[e];
        int4   sB = *(const int4*)&g_esrc[e + 4];
        float4 nA = *(const float4*)&g_enorm[e];
        float4 nB = *(const float4*)&g_enorm[e + 4];
        float2 h0 = H2[(size_t)sA.x * 32 + lane];
        float2 h1 = H2[(size_t)sA.y * 32 + lane];
        float2 h2 = H2[(size_t)sA.z * 32 + lane];
        float2 h3 = H2[(size_t)sA.w * 32 + lane];
        float2 h4 = H2[(size_t)sB.x * 32 + lane];
        float2 h5 = H2[(size_t)sB.y * 32 + lane];
        float2 h6 = H2[(size_t)sB.z * 32 + lane];
        float2 h7 = H2[(size_t)sB.w * 32 + lane];
        ax = fmaf(h0.x, nA.x, ax); ay = fmaf(h0.y, nA.x, ay);
        ax = fmaf(h1.x, nA.y, ax); ay = fmaf(h1.y, nA.y, ay);
        ax = fmaf(h2.x, nA.z, ax); ay = fmaf(h2.y, nA.z, ay);
        ax = fmaf(h3.x, nA.w, ax); ay = fmaf(h3.y, nA.w, ay);
        ax = fmaf(h4.x, nB.x, ax); ay = fmaf(h4.y, nB.x, ay);
        ax = fmaf(h5.x, nB.y, ax); ay = fmaf(h5.y, nB.y, ay);
        ax = fmaf(h6.x, nB.z, ax); ay = fmaf(h6.y, nB.z, ay);
        ax = fmaf(h7.x, nB.w, ax); ay = fmaf(h7.y, nB.w, ay);
    }
    if (e + 4 <= e1) {
        int4   sA = *(const int4*)&g_esrc[e];
        float4 nA = *(const float4*)&g_enorm[e];
        float2 h0 = H2[(size_t)sA.x * 32 + lane];
        float2 h1 = H2[(size_t)sA.y * 32 + lane];
        float2 h2 = H2[(size_t)sA.z * 32 + lane];
        float2 h3 = H2[(size_t)sA.w * 32 + lane];
        ax = fmaf(h0.x, nA.x, ax); ay = fmaf(h0.y, nA.x, ay);
        ax = fmaf(h1.x, nA.y, ax); ay = fmaf(h1.y, nA.y, ay);
        ax = fmaf(h2.x, nA.z, ax); ay = fmaf(h2.y, nA.z, ay);
        ax = fmaf(h3.x, nA.w, ax); ay = fmaf(h3.y, nA.w, ay);
        e += 4;
    }
    for (; e < e1; e++) {
        int s = g_esrc[e]; float nm = g_enorm[e];
        float2 hv = H2[(size_t)s * 32 + lane];
        ax = fmaf(hv.x, nm, ax); ay = fmaf(hv.y, nm, ay);
    }
    if (LAYER == 0) { ax = fmaxf(ax, 0.0f); ay = fmaxf(ay, 0.0f); }
    O2[(size_t)node * 32 + lane] = make_float2(ax, ay);
}

// -------- host launch (kernel launches ONLY; graph-capture safe) --------
extern "C" void kernel_launch(void* const* d_in, const int* in_sizes, int n_in,
                              void* d_out, int out_size)
{
    const float* x  = (const float*)d_in[0];
    const int*   ei = (const int*)d_in[1];     // dtype resolved on device
    const float* W1 = (const float*)d_in[2];
    const float* b1 = (const float*)d_in[3];
    const float* W2 = (const float*)d_in[4];
    const float* b2 = (const float*)d_in[5];
    float* out = (float*)d_out;

    int n = in_sizes[0] / FD;      // 100000
    int E = in_sizes[1] / 2;       // 1600000

    int gG  = (n + FD - 1) / FD;               // 64 rows per gemm block
    int gAg = (n * 32 + 255) / 256;            // warp per node

    k_preprocess<<<NBLK, TPB>>>(ei, n, E);

    k_gemm<0><<<gG, 64>>>(x, W1, n);
    k_aggregate<0><<<gAg, 256>>>(b1, nullptr, n);

    k_gemm<1><<<gG, 64>>>(nullptr, W2, n);
    k_aggregate<1><<<gAg, 256>>>(b2, out, n);
}